// round 1
// baseline (speedup 1.0000x reference)
#include <cuda_runtime.h>

#define B_ 8
#define C_ 32
#define N_ 4096
#define NT 128

// exp(mean_c x[b,c,n]) per (b,n)
__device__ float g_e[B_ * N_];

__global__ void mean_exp_kernel(const float* __restrict__ x) {
    int idx = blockIdx.x * blockDim.x + threadIdx.x;
    if (idx >= B_ * N_) return;
    int b = idx >> 12;
    int n = idx & (N_ - 1);
    const float* p = x + ((size_t)b * C_) * N_ + n;
    float s = 0.f;
#pragma unroll
    for (int c = 0; c < C_; c++) s += p[(size_t)c * N_];
    g_e[idx] = __expf(s * (1.0f / C_));
}

// Fused: out[b,c,m] = relu( para[c,m] * sum_n fea[b,c,n] * adj[n,m] * w(n,m) )
// w(n,m) = 2*min(e_n,e_m)/(e_n+e_m)   (== |abs(abs(sigmoid(d)-0.5)-0.5)|*2, symmetric)
__global__ __launch_bounds__(128, 4)
void gcn_fused_kernel(const float* __restrict__ x,
                      const float* __restrict__ para,
                      const float* __restrict__ adj,
                      float* __restrict__ out) {
    __shared__ float s_fea[NT][34];   // [n][c], padded row (34 floats, 8B-aligned rows)
    __shared__ float s_e[NT];

    const int tid = threadIdx.x;
    const int b = blockIdx.y;
    const int m = blockIdx.x * 128 + tid;

    const float em = g_e[b * N_ + m];

    unsigned long long acc[16];
#pragma unroll
    for (int p = 0; p < 16; p++) acc[p] = 0ull;

    const float* xb = x + (size_t)b * C_ * N_;

    for (int n0 = 0; n0 < N_; n0 += NT) {
        __syncthreads();
        // stage fea tile: s_fea[i][c] = x[b,c,n0+i]  (coalesced gmem reads)
#pragma unroll
        for (int k = 0; k < (C_ * NT) / 128; k++) {
            int idx = k * 128 + tid;
            int c = idx / NT;
            int i = idx % NT;
            s_fea[i][c] = xb[(size_t)c * N_ + n0 + i];
        }
        s_e[tid] = g_e[b * N_ + n0 + tid];
        __syncthreads();

        const float* adj_p = adj + (size_t)n0 * N_ + m;
#pragma unroll 4
        for (int n = 0; n < NT; n++) {
            float en = s_e[n];
            float adjv = __ldg(adj_p + (size_t)n * N_);
            float sum = en + em;
            float mn = fminf(en, em);
            float w = __fdividef(mn, sum) * (2.0f * adjv);
            unsigned long long w2;
            asm("mov.b64 %0, {%1, %1};" : "=l"(w2) : "f"(w));
            const unsigned long long* row =
                reinterpret_cast<const unsigned long long*>(&s_fea[n][0]);
#pragma unroll
            for (int p = 0; p < 16; p++) {
                asm("fma.rn.f32x2 %0, %1, %2, %0;"
                    : "+l"(acc[p])
                    : "l"(row[p]), "l"(w2));
            }
        }
    }

    // epilogue: * para, relu, store (coalesced per channel)
#pragma unroll
    for (int p = 0; p < 16; p++) {
        float lo, hi;
        asm("mov.b64 {%0, %1}, %2;" : "=f"(lo), "=f"(hi) : "l"(acc[p]));
        int c0 = 2 * p, c1 = 2 * p + 1;
        float v0 = lo * para[c0 * N_ + m];
        float v1 = hi * para[c1 * N_ + m];
        out[((size_t)b * C_ + c0) * N_ + m] = fmaxf(v0, 0.0f);
        out[((size_t)b * C_ + c1) * N_ + m] = fmaxf(v1, 0.0f);
    }
}

extern "C" void kernel_launch(void* const* d_in, const int* in_sizes, int n_in,
                              void* d_out, int out_size) {
    const float* x    = (const float*)d_in[0];  // [8,32,64,64]
    const float* para = (const float*)d_in[1];  // [1,32,64,64]
    const float* adj  = (const float*)d_in[2];  // [4096,4096]
    float* out = (float*)d_out;                 // [8,32,64,64]

    mean_exp_kernel<<<(B_ * N_ + 255) / 256, 256>>>(x);

    dim3 grid(N_ / 128, B_);
    gcn_fused_kernel<<<grid, 128>>>(x, para, adj, out);
}

// round 2
// speedup vs baseline: 1.6621x; 1.6621x over previous
#include <cuda_runtime.h>

#define B_ 8
#define C_ 32
#define N_ 4096
#define NT 256
#define SPLIT 2

// exp(mean_c x[b,c,n]) per (b,n)
__device__ float g_e[B_ * N_];
// split-K partial sums: [split][b][c][n]
__device__ float g_part[SPLIT][B_ * C_ * N_];

__global__ void mean_exp_kernel(const float* __restrict__ x) {
    int idx = blockIdx.x * blockDim.x + threadIdx.x;
    if (idx >= B_ * N_) return;
    int b = idx >> 12;
    int n = idx & (N_ - 1);
    const float* p = x + ((size_t)b * C_) * N_ + n;
    float s = 0.f;
#pragma unroll
    for (int c = 0; c < C_; c++) s += p[(size_t)c * N_];
    g_e[idx] = __expf(s * (1.0f / C_));
}

// Partial: g_part[z][b,c,m] = sum_{n in z-slice} fea[b,c,n] * adj[n,m] * w(n,m)
// w(n,m) = 2*min(e_n,e_m)/(e_n+e_m)
__global__ __launch_bounds__(128, 4)
void gcn_partial_kernel(const float* __restrict__ x,
                        const float* __restrict__ adj) {
    __shared__ float s_fea[NT][36];   // row stride 144B: 16B-aligned, STS.128 conflict-free
    __shared__ float s_e[NT];

    const int tid = threadIdx.x;
    const int b = blockIdx.y;
    const int z = blockIdx.z;
    const int m = blockIdx.x * 128 + tid;

    const float em = g_e[b * N_ + m];

    unsigned long long acc[16];
#pragma unroll
    for (int p = 0; p < 16; p++) acc[p] = 0ull;

    const float* xb = x + (size_t)b * C_ * N_;
    const int nbeg = z * (N_ / SPLIT);
    const int nend = nbeg + (N_ / SPLIT);

    for (int n0 = nbeg; n0 < nend; n0 += NT) {
        __syncthreads();
        // stage fea tile: s_fea[i][c] = x[b,c,n0+i], vectorized STS.128 over 4 channels
#pragma unroll
        for (int r = 0; r < NT / 128; r++) {
            int i = tid + r * 128;
#pragma unroll
            for (int k = 0; k < C_ / 4; k++) {
                float4 v;
                v.x = xb[(size_t)(4 * k + 0) * N_ + n0 + i];
                v.y = xb[(size_t)(4 * k + 1) * N_ + n0 + i];
                v.z = xb[(size_t)(4 * k + 2) * N_ + n0 + i];
                v.w = xb[(size_t)(4 * k + 3) * N_ + n0 + i];
                *reinterpret_cast<float4*>(&s_fea[i][4 * k]) = v;
            }
            s_e[i] = g_e[b * N_ + n0 + i];
        }
        __syncthreads();

        const float* adj_p = adj + (size_t)n0 * N_ + m;
#pragma unroll 4
        for (int n = 0; n < NT; n++) {
            float en = s_e[n];
            float adjv = __ldg(adj_p + (size_t)n * N_);
            float sum = en + em;
            float mn = fminf(en, em);
            float w = __fdividef(mn, sum) * (2.0f * adjv);
            unsigned long long w2;
            asm("mov.b64 %0, {%1, %1};" : "=l"(w2) : "f"(w));
            unsigned row_addr =
                (unsigned)__cvta_generic_to_shared(&s_fea[n][0]);
#pragma unroll
            for (int p = 0; p < 8; p++) {
                unsigned long long d0, d1;
                asm("ld.shared.v2.u64 {%0, %1}, [%2];"
                    : "=l"(d0), "=l"(d1) : "r"(row_addr + 16 * p));
                asm("fma.rn.f32x2 %0, %1, %2, %0;"
                    : "+l"(acc[2 * p]) : "l"(d0), "l"(w2));
                asm("fma.rn.f32x2 %0, %1, %2, %0;"
                    : "+l"(acc[2 * p + 1]) : "l"(d1), "l"(w2));
            }
        }
    }

    // write partials (no para/relu here)
    float* dst = &g_part[z][((size_t)b * C_) * N_ + m];
#pragma unroll
    for (int p = 0; p < 16; p++) {
        float lo, hi;
        asm("mov.b64 {%0, %1}, %2;" : "=f"(lo), "=f"(hi) : "l"(acc[p]));
        dst[(size_t)(2 * p) * N_] = lo;
        dst[(size_t)(2 * p + 1) * N_] = hi;
    }
}

// out = relu(para * (part0 + part1)), vectorized float4
__global__ void combine_kernel(const float* __restrict__ para,
                               float* __restrict__ out) {
    int idx = blockIdx.x * blockDim.x + threadIdx.x;  // over B*C*N/4
    const float4* p0 = reinterpret_cast<const float4*>(g_part[0]);
    const float4* p1 = reinterpret_cast<const float4*>(g_part[1]);
    const float4* pp = reinterpret_cast<const float4*>(para);
    float4 a = p0[idx];
    float4 c = p1[idx];
    float4 pv = pp[idx & (C_ * N_ / 4 - 1)];
    float4 o;
    o.x = fmaxf((a.x + c.x) * pv.x, 0.f);
    o.y = fmaxf((a.y + c.y) * pv.y, 0.f);
    o.z = fmaxf((a.z + c.z) * pv.z, 0.f);
    o.w = fmaxf((a.w + c.w) * pv.w, 0.f);
    reinterpret_cast<float4*>(out)[idx] = o;
}

extern "C" void kernel_launch(void* const* d_in, const int* in_sizes, int n_in,
                              void* d_out, int out_size) {
    const float* x    = (const float*)d_in[0];  // [8,32,64,64]
    const float* para = (const float*)d_in[1];  // [1,32,64,64]
    const float* adj  = (const float*)d_in[2];  // [4096,4096]
    float* out = (float*)d_out;                 // [8,32,64,64]

    mean_exp_kernel<<<(B_ * N_ + 255) / 256, 256>>>(x);

    dim3 grid(N_ / 128, B_, SPLIT);
    gcn_partial_kernel<<<grid, 128>>>(x, adj);

    combine_kernel<<<(B_ * C_ * N_ / 4) / 256, 256>>>(para, out);
}